// round 15
// baseline (speedup 1.0000x reference)
#include <cuda_runtime.h>
#include <cuda_fp16.h>

#define N_NODES 50000
#define N_EDGES 800000
#define N_GRAPHS 512
#define IN_CH 128
#define HID 64
#define HHALF 32
#define EQ4 (N_EDGES / 4)

// ---------------- scratch (device globals) ----------------
__device__ float  g_xw[N_NODES * HID];    // fp32 xW1 (exact, self-loop term)
__device__ __half g_xwh[N_NODES * HID];   // fp16 xW1 (gather payload)
__device__ __half g_h1h[N_NODES * HID];   // fp16 conv1 message sums
__device__ __half g_h2h[N_NODES * HID];   // fp16 relu(h1)W2 (gather payload)
__device__ __half g_h3h[N_NODES * HID];   // fp16 conv2 out
__device__ float  g_deg[N_NODES];
__device__ float  g_dinv[N_NODES];
__device__ float  g_coef[N_EDGES];
__device__ float  g_pool[N_GRAPHS * HID];
__device__ float  g_cnt[N_GRAPHS];

__device__ __forceinline__ void red_add_v4f32(float* addr, float a, float b,
                                              float c, float d) {
    asm volatile("red.global.add.v4.f32 [%0], {%1, %2, %3, %4};"
                 :: "l"(addr), "f"(a), "f"(b), "f"(c), "f"(d) : "memory");
}

__device__ __forceinline__ void red_add_v4f16x2(__half* addr, unsigned r0,
                                                unsigned r1, unsigned r2,
                                                unsigned r3) {
    asm volatile("red.global.add.noftz.v4.f16x2 [%0], {%1, %2, %3, %4};"
                 :: "l"(addr), "r"(r0), "r"(r1), "r"(r2), "r"(r3) : "memory");
}

// ---------------- degree / norm (side stream) ----------------
__global__ void deg_kernel(const int* __restrict__ dst,
                           const float* __restrict__ ew) {
    int e = blockIdx.x * blockDim.x + threadIdx.x;
    if (e < N_EDGES) atomicAdd(&g_deg[dst[e]], ew[e]);
}

__global__ void dinv_kernel() {
    int i = blockIdx.x * blockDim.x + threadIdx.x;
    if (i < N_NODES) g_dinv[i] = rsqrtf(g_deg[i] + 1.0f);
}

__global__ void coef_kernel(const int* __restrict__ src,
                            const int* __restrict__ dst,
                            const float* __restrict__ ew) {
    int e = blockIdx.x * blockDim.x + threadIdx.x;
    if (e < N_EDGES)
        g_coef[e] = g_dinv[src[e]] * ew[e] * g_dinv[dst[e]];
}

// ---------------- GEMM1 half: [64,128]@[128,32] per block -------------------
// 256 threads, 2 rows x 4 cols per thread. smem 48KB.
#define TM 64
__global__ void __launch_bounds__(256) gemm1_half(const float* __restrict__ x,
                                                  const float* __restrict__ W,
                                                  int col0) {
    __shared__ float Ws[IN_CH * HHALF];   // 16 KB
    __shared__ float Xs[TM * IN_CH];      // 32 KB
    int tid = threadIdx.x;
    int row0 = blockIdx.x * TM;

    for (int i = tid; i < IN_CH * HHALF / 4; i += 256) {
        int k  = i >> 3;
        int c4 = (i & 7) * 4;
        *(float4*)&Ws[k * HHALF + c4] = *(const float4*)&W[k * HID + col0 + c4];
    }
    for (int i = tid; i < TM * (IN_CH / 4); i += 256) {
        int r  = i >> 5;
        int c4 = (i & 31) * 4;
        int node = row0 + r;
        float4 v = (node < N_NODES)
                 ? *(const float4*)&x[(long long)node * IN_CH + c4]
                 : make_float4(0.f, 0.f, 0.f, 0.f);
        *(float4*)&Xs[r * IN_CH + c4] = v;
    }
    __syncthreads();

    int ty = tid >> 3;          // 0..31 -> rows ty*2, ty*2+1
    int tx = tid & 7;           // 0..7  -> cols tx*4 of the half
    float4 acc0 = make_float4(0,0,0,0), acc1 = acc0;
    const float* xrow = &Xs[(ty * 2) * IN_CH];

    #pragma unroll 4
    for (int k = 0; k < IN_CH; k++) {
        float4 w = *(const float4*)&Ws[k * HHALF + tx * 4];
        float x0 = xrow[k];
        float x1 = xrow[IN_CH + k];
        acc0.x += x0*w.x; acc0.y += x0*w.y; acc0.z += x0*w.z; acc0.w += x0*w.w;
        acc1.x += x1*w.x; acc1.y += x1*w.y; acc1.z += x1*w.z; acc1.w += x1*w.w;
    }

    float4 accs[2] = {acc0, acc1};
    #pragma unroll
    for (int i = 0; i < 2; i++) {
        int node = row0 + ty * 2 + i;
        if (node < N_NODES) {
            int off = node * HID + col0 + tx * 4;
            *(float4*)&g_xw[off] = accs[i];
            __half2 h01 = __floats2half2_rn(accs[i].x, accs[i].y);
            __half2 h23 = __floats2half2_rn(accs[i].z, accs[i].w);
            uint2 raw;
            raw.x = *(const unsigned*)&h01;
            raw.y = *(const unsigned*)&h23;
            *(uint2*)&g_xwh[off] = raw;
        }
    }
}

// ---------------- GEMM2 half: relu(h1msg + dinv^2*xw + b1) @ W2[:,col0:+32] -
__global__ void __launch_bounds__(256) gemm2_half(const float* __restrict__ W,
                                                  const float* __restrict__ b1,
                                                  const float* __restrict__ b2,
                                                  int col0) {
    __shared__ float Ws[HID * HHALF];     // 8 KB
    __shared__ float Xs[TM * HID];        // 16 KB
    int tid = threadIdx.x;
    int row0 = blockIdx.x * TM;

    for (int i = tid; i < HID * HHALF / 4; i += 256) {
        int k  = i >> 3;
        int c4 = (i & 7) * 4;
        *(float4*)&Ws[k * HHALF + c4] = *(const float4*)&W[k * HID + col0 + c4];
    }
    for (int i = tid; i < TM * (HID / 4); i += 256) {
        int r  = i >> 4;
        int c4 = (i & 15) * 4;
        int node = row0 + r;
        float4 v = make_float4(0.f, 0.f, 0.f, 0.f);
        if (node < N_NODES) {
            float di = g_dinv[node];
            float dd = di * di;
            float4 xwv = *(const float4*)&g_xw[node * HID + c4];
            uint2 mraw = *(const uint2*)&g_h1h[node * HID + c4];
            float2 m01 = __half22float2(*reinterpret_cast<const __half2*>(&mraw.x));
            float2 m23 = __half22float2(*reinterpret_cast<const __half2*>(&mraw.y));
            float4 bb = *(const float4*)&b1[c4];
            v = make_float4(fmaxf(m01.x + dd*xwv.x + bb.x, 0.f),
                            fmaxf(m01.y + dd*xwv.y + bb.y, 0.f),
                            fmaxf(m23.x + dd*xwv.z + bb.z, 0.f),
                            fmaxf(m23.y + dd*xwv.w + bb.w, 0.f));
        }
        *(float4*)&Xs[r * HID + c4] = v;
    }
    __syncthreads();

    int ty = tid >> 3;
    int tx = tid & 7;
    float4 acc0 = make_float4(0,0,0,0), acc1 = acc0;
    const float* xrow = &Xs[(ty * 2) * HID];
    #pragma unroll 4
    for (int k = 0; k < HID; k++) {
        float4 w = *(const float4*)&Ws[k * HHALF + tx * 4];
        float x0 = xrow[k];
        float x1 = xrow[HID + k];
        acc0.x += x0*w.x; acc0.y += x0*w.y; acc0.z += x0*w.z; acc0.w += x0*w.w;
        acc1.x += x1*w.x; acc1.y += x1*w.y; acc1.z += x1*w.z; acc1.w += x1*w.w;
    }
    float4 bb = *(const float4*)&b2[col0 + tx * 4];
    float4 accs[2] = {acc0, acc1};
    #pragma unroll
    for (int i = 0; i < 2; i++) {
        int node = row0 + ty * 2 + i;
        if (node < N_NODES) {
            int off = node * HID + col0 + tx * 4;
            __half2 p01 = __floats2half2_rn(accs[i].x, accs[i].y);
            __half2 p23 = __floats2half2_rn(accs[i].z, accs[i].w);
            uint2 praw;
            praw.x = *(const unsigned*)&p01;
            praw.y = *(const unsigned*)&p23;
            *(uint2*)&g_h2h[off] = praw;
            float di = g_dinv[node];
            float dd = di * di;
            __half2 s01 = __floats2half2_rn(dd*accs[i].x + bb.x, dd*accs[i].y + bb.y);
            __half2 s23 = __floats2half2_rn(dd*accs[i].z + bb.z, dd*accs[i].w + bb.w);
            uint2 sraw;
            sraw.x = *(const unsigned*)&s01;
            sraw.y = *(const unsigned*)&s23;
            *(uint2*)&g_h3h[off] = sraw;
        }
    }
}

// ---------------- edge scatter half (32 channels at col0) -------------------
// 4 threads per edge (8 ch each); 4 independent edges per thread (MLP=4).
__global__ void __launch_bounds__(256) scatter_half(const int* __restrict__ src,
                                                    const int* __restrict__ dst,
                                                    const __half* __restrict__ in,
                                                    __half* __restrict__ out,
                                                    int col0) {
    int idx = blockIdx.x * blockDim.x + threadIdx.x;   // < EQ4*4 = 800k
    if (idx >= EQ4 * 4) return;
    int e0 = idx >> 2;
    int c8 = (idx & 3) * 8 + col0;

    float cf[4];
    int   s[4], d[4];
    #pragma unroll
    for (int j = 0; j < 4; j++) {
        int e = e0 + j * EQ4;
        cf[j] = g_coef[e];
        s[j]  = src[e];
        d[j]  = dst[e];
    }
    uint4 raw[4];
    #pragma unroll
    for (int j = 0; j < 4; j++)
        raw[j] = *(const uint4*)(in + (long long)s[j] * HID + c8);
    #pragma unroll
    for (int j = 0; j < 4; j++) {
        __half2 ch = __float2half2_rn(cf[j]);
        __half2 m0 = __hmul2(*reinterpret_cast<const __half2*>(&raw[j].x), ch);
        __half2 m1 = __hmul2(*reinterpret_cast<const __half2*>(&raw[j].y), ch);
        __half2 m2 = __hmul2(*reinterpret_cast<const __half2*>(&raw[j].z), ch);
        __half2 m3 = __hmul2(*reinterpret_cast<const __half2*>(&raw[j].w), ch);
        red_add_v4f16x2(out + (long long)d[j] * HID + c8,
                        *(const unsigned*)&m0, *(const unsigned*)&m1,
                        *(const unsigned*)&m2, *(const unsigned*)&m3);
    }
}

// ---------------- pooling ----------------
__global__ void pool_kernel(const int* __restrict__ batch) {
    int idx = blockIdx.x * blockDim.x + threadIdx.x;
    if (idx < N_NODES * 16) {
        int i  = idx >> 4;
        int c4 = (idx & 15) * 4;
        int g = batch[i];
        uint2 raw = *(const uint2*)&g_h3h[i * HID + c4];
        float2 v01 = __half22float2(*reinterpret_cast<const __half2*>(&raw.x));
        float2 v23 = __half22float2(*reinterpret_cast<const __half2*>(&raw.y));
        red_add_v4f32(&g_pool[g * HID + c4], v01.x, v01.y, v23.x, v23.y);
        if (c4 == 0) atomicAdd(&g_cnt[g], 1.0f);
    }
}

// ---------------- head ----------------
__global__ void head_kernel(const float* __restrict__ LW1,
                            const float* __restrict__ Lb1,
                            const float* __restrict__ LW2,
                            const float* __restrict__ Lb2,
                            float* __restrict__ out) {
    int g = blockIdx.x;
    int t = threadIdx.x;
    __shared__ float p[HID];
    __shared__ float h[32];
    float cnt = fmaxf(g_cnt[g], 1.0f);
    p[t]      = g_pool[g * HID + t] / cnt;
    p[t + 32] = g_pool[g * HID + 32 + t] / cnt;
    __syncwarp();
    float acc = Lb1[t];
    #pragma unroll
    for (int k = 0; k < HID; k++) acc += p[k] * LW1[k * 32 + t];
    h[t] = acc;
    __syncwarp();
    if (t < 10) {
        float o = Lb2[t];
        #pragma unroll
        for (int j = 0; j < 32; j++) o += h[j] * LW2[j * 10 + t];
        out[g * 10 + t] = o;
    }
}

// ---------------- launch ----------------
extern "C" void kernel_launch(void* const* d_in, const int* in_sizes, int n_in,
                              void* d_out, int out_size) {
    const float* x     = (const float*)d_in[0];
    const int*   ei    = (const int*)d_in[1];
    const float* ew    = (const float*)d_in[2];
    const int*   batch = (const int*)d_in[3];
    const float* W1    = (const float*)d_in[4];
    const float* b1    = (const float*)d_in[5];
    const float* W2    = (const float*)d_in[6];
    const float* b2    = (const float*)d_in[7];
    const float* LW1   = (const float*)d_in[8];
    const float* Lb1   = (const float*)d_in[9];
    const float* LW2   = (const float*)d_in[10];
    const float* Lb2   = (const float*)d_in[11];
    float* out = (float*)d_out;

    const int* src = ei;
    const int* dst = ei + N_EDGES;

    void *p_deg, *p_pool, *p_cnt, *p_h1h;
    cudaGetSymbolAddress(&p_deg,  g_deg);
    cudaGetSymbolAddress(&p_pool, g_pool);
    cudaGetSymbolAddress(&p_cnt,  g_cnt);
    cudaGetSymbolAddress(&p_h1h,  g_h1h);

    __half *xwh, *h1h, *h2h, *h3h;
    cudaGetSymbolAddress((void**)&xwh, g_xwh);
    cudaGetSymbolAddress((void**)&h1h, g_h1h);
    cudaGetSymbolAddress((void**)&h2h, g_h2h);
    cudaGetSymbolAddress((void**)&h3h, g_h3h);

    static cudaStream_t s1 = nullptr;
    static cudaEvent_t evFork = nullptr, evG1a = nullptr, evS1a = nullptr,
                       evG2a = nullptr, evS2a = nullptr;
    static bool init_done = false;
    if (!init_done) {
        cudaStreamCreateWithFlags(&s1, cudaStreamNonBlocking);
        cudaEventCreateWithFlags(&evFork, cudaEventDisableTiming);
        cudaEventCreateWithFlags(&evG1a,  cudaEventDisableTiming);
        cudaEventCreateWithFlags(&evS1a,  cudaEventDisableTiming);
        cudaEventCreateWithFlags(&evG2a,  cudaEventDisableTiming);
        cudaEventCreateWithFlags(&evS2a,  cudaEventDisableTiming);
        cudaFuncSetAttribute(gemm1_half,
                             cudaFuncAttributePreferredSharedMemoryCarveout, 100);
        cudaFuncSetAttribute(gemm2_half,
                             cudaFuncAttributePreferredSharedMemoryCarveout, 100);
        init_done = true;
    }

    int gblocks = (N_NODES + TM - 1) / TM;
    int sblocks = (EQ4 * 4 + 255) / 256;

    // ---- fork: prep chain on s1 ∥ gemm1a+gemm1b on s0 ----
    cudaEventRecord(evFork, 0);
    cudaStreamWaitEvent(s1, evFork, 0);

    cudaMemsetAsync(p_deg,  0, N_NODES * sizeof(float), s1);
    cudaMemsetAsync(p_h1h,  0, N_NODES * HID * sizeof(__half), s1);
    cudaMemsetAsync(p_pool, 0, N_GRAPHS * HID * sizeof(float), s1);
    cudaMemsetAsync(p_cnt,  0, N_GRAPHS * sizeof(float), s1);
    deg_kernel<<<(N_EDGES + 255) / 256, 256, 0, s1>>>(dst, ew);
    dinv_kernel<<<(N_NODES + 255) / 256, 256, 0, s1>>>();
    coef_kernel<<<(N_EDGES + 255) / 256, 256, 0, s1>>>(src, dst, ew);
    // (s1 now holds: prep done)

    gemm1_half<<<gblocks, 256>>>(x, W1, 0);           // s0: cols 0-31
    cudaEventRecord(evG1a, 0);
    gemm1_half<<<gblocks, 256>>>(x, W1, HHALF);       // s0: cols 32-63

    // scatter1a on s1 (after prep, after gemm1a) ∥ gemm1b on s0
    cudaStreamWaitEvent(s1, evG1a, 0);
    scatter_half<<<sblocks, 256, 0, s1>>>(src, dst, xwh, h1h, 0);
    cudaEventRecord(evS1a, s1);

    // scatter1b on s0 (after gemm1b by order; needs coef -> wait prep via evS1a? No:
    // prep completion is ordered before evS1a on s1, but scatter1b needs coef too.
    // Wait on evS1a would over-serialize; instead wait a dedicated prep event.)
    // -- we use evS1a for gemm2a; scatter1b waits on prep through s1's scatter1a
    //    ONLY via evS1a. To keep scatter1b correct it must see coef: record is
    //    implicit since scatter1a started after coef on s1; but scatter1b is on s0.
    cudaStreamWaitEvent(0, evS1a, 0);                 // safe: also implies prep done
    scatter_half<<<sblocks, 256>>>(src, dst, xwh, h1h, HHALF);

    // conv2: gemm2a needs full h1h (scatter1a via evS1a already waited; scatter1b s0 order)
    gemm2_half<<<gblocks, 256>>>(W2, b1, b2, 0);
    cudaEventRecord(evG2a, 0);
    gemm2_half<<<gblocks, 256>>>(W2, b1, b2, HHALF);

    cudaStreamWaitEvent(s1, evG2a, 0);
    scatter_half<<<sblocks, 256, 0, s1>>>(src, dst, h2h, h3h, 0);
    cudaEventRecord(evS2a, s1);

    scatter_half<<<sblocks, 256>>>(src, dst, h2h, h3h, HHALF);

    cudaStreamWaitEvent(0, evS2a, 0);
    pool_kernel<<<(N_NODES * 16 + 255) / 256, 256>>>(batch);
    head_kernel<<<N_GRAPHS, 32>>>(LW1, Lb1, LW2, Lb2, out);
}

// round 16
// speedup vs baseline: 1.3312x; 1.3312x over previous
#include <cuda_runtime.h>
#include <cuda_fp16.h>

#define N_NODES 50000
#define N_EDGES 800000
#define N_GRAPHS 512
#define IN_CH 128
#define HID 64
#define EQ4 (N_EDGES / 4)

// ---------------- scratch (device globals) ----------------
__device__ float  g_xw[N_NODES * HID];    // fp32 xW1 (exact, self-loop term)
__device__ __half g_xwh[N_NODES * HID];   // fp16 xW1 (gather payload)
__device__ __half g_h1h[N_NODES * HID];   // fp16 conv1 message sums
__device__ __half g_h2h[N_NODES * HID];   // fp16 relu(h1)W2 (gather payload)
__device__ __half g_h3h[N_NODES * HID];   // fp16 conv2 out (self-loop + msgs)
__device__ float  g_deg[N_NODES];
__device__ float  g_dinv[N_NODES];
__device__ float  g_coef[N_EDGES];
__device__ float  g_pool[N_GRAPHS * HID];
__device__ float  g_cnt[N_GRAPHS];

__device__ __forceinline__ void red_add_v4f32(float* addr, float a, float b,
                                              float c, float d) {
    asm volatile("red.global.add.v4.f32 [%0], {%1, %2, %3, %4};"
                 :: "l"(addr), "f"(a), "f"(b), "f"(c), "f"(d) : "memory");
}

// 8 fp16 channels per 16B reduction
__device__ __forceinline__ void red_add_v4f16x2(__half* addr, unsigned r0,
                                                unsigned r1, unsigned r2,
                                                unsigned r3) {
    asm volatile("red.global.add.noftz.v4.f16x2 [%0], {%1, %2, %3, %4};"
                 :: "l"(addr), "r"(r0), "r"(r1), "r"(r2), "r"(r3) : "memory");
}

// ---------------- degree / norm / counts (side stream) ----------------
__global__ void deg_kernel(const int* __restrict__ dst,
                           const float* __restrict__ ew) {
    int e = blockIdx.x * blockDim.x + threadIdx.x;
    if (e < N_EDGES) atomicAdd(&g_deg[dst[e]], ew[e]);
}

__global__ void dinv_kernel() {
    int i = blockIdx.x * blockDim.x + threadIdx.x;
    if (i < N_NODES) g_dinv[i] = rsqrtf(g_deg[i] + 1.0f);
}

__global__ void coef_kernel(const int* __restrict__ src,
                            const int* __restrict__ dst,
                            const float* __restrict__ ew) {
    int e = blockIdx.x * blockDim.x + threadIdx.x;
    if (e < N_EDGES)
        g_coef[e] = g_dinv[src[e]] * ew[e] * g_dinv[dst[e]];
}

__global__ void cnt_kernel(const int* __restrict__ batch) {
    int i = blockIdx.x * blockDim.x + threadIdx.x;
    if (i < N_NODES) atomicAdd(&g_cnt[batch[i]], 1.0f);
}

// ---------------- GEMM 1 (fp32): [N,128]@[128,64] -> g_xw + g_xwh -----------
#define TM 64
#define KH 64
__global__ void __launch_bounds__(256) gemm1_kernel(const float* __restrict__ x,
                                                    const float* __restrict__ W) {
    __shared__ float Ws[KH * HID];       // 16 KB
    __shared__ float Xs[TM * IN_CH];     // 32 KB
    int tid = threadIdx.x;
    int row0 = blockIdx.x * TM;

    for (int i = tid; i < TM * (IN_CH / 4); i += 256) {
        int r  = i >> 5;
        int c4 = (i & 31) * 4;
        int node = row0 + r;
        float4 v = (node < N_NODES)
                 ? *(const float4*)&x[(long long)node * IN_CH + c4]
                 : make_float4(0.f, 0.f, 0.f, 0.f);
        *(float4*)&Xs[r * IN_CH + c4] = v;
    }

    int ty = tid >> 4;
    int tx = tid & 15;
    float4 acc0 = make_float4(0,0,0,0), acc1 = acc0, acc2 = acc0, acc3 = acc0;
    const float* xrow = &Xs[(ty * 4) * IN_CH];

    #pragma unroll
    for (int half = 0; half < 2; half++) {
        __syncthreads();
        for (int i = tid; i < KH * HID / 4; i += 256)
            *(float4*)&Ws[i * 4] = *(const float4*)&W[half * KH * HID + i * 4];
        __syncthreads();
        int kb = half * KH;
        #pragma unroll 4
        for (int k = 0; k < KH; k++) {
            float4 w = *(const float4*)&Ws[k * HID + tx * 4];
            float x0 = xrow[kb + k];
            float x1 = xrow[IN_CH + kb + k];
            float x2 = xrow[2 * IN_CH + kb + k];
            float x3 = xrow[3 * IN_CH + kb + k];
            acc0.x += x0*w.x; acc0.y += x0*w.y; acc0.z += x0*w.z; acc0.w += x0*w.w;
            acc1.x += x1*w.x; acc1.y += x1*w.y; acc1.z += x1*w.z; acc1.w += x1*w.w;
            acc2.x += x2*w.x; acc2.y += x2*w.y; acc2.z += x2*w.z; acc2.w += x2*w.w;
            acc3.x += x3*w.x; acc3.y += x3*w.y; acc3.z += x3*w.z; acc3.w += x3*w.w;
        }
    }

    float4 accs[4] = {acc0, acc1, acc2, acc3};
    #pragma unroll
    for (int i = 0; i < 4; i++) {
        int node = row0 + ty * 4 + i;
        if (node < N_NODES) {
            *(float4*)&g_xw[node * HID + tx * 4] = accs[i];
            __half2 h01 = __floats2half2_rn(accs[i].x, accs[i].y);
            __half2 h23 = __floats2half2_rn(accs[i].z, accs[i].w);
            uint2 raw;
            raw.x = *(const unsigned*)&h01;
            raw.y = *(const unsigned*)&h23;
            *(uint2*)&g_xwh[node * HID + tx * 4] = raw;
        }
    }
}

// ---------------- GEMM 2: in = relu(h1msg + dinv^2*xw + b1) -----------------
// -> g_h2h (fp16 payload) + g_h3h (self-loop + bias init, fp16)
__global__ void __launch_bounds__(256) gemm2_kernel(const float* __restrict__ W,
                                                    const float* __restrict__ b1,
                                                    const float* __restrict__ b2) {
    __shared__ float Ws[HID * HID];
    __shared__ float Xs[TM * HID];
    int tid = threadIdx.x;
    int row0 = blockIdx.x * TM;

    for (int i = tid; i < HID * HID / 4; i += 256)
        *(float4*)&Ws[i * 4] = *(const float4*)&W[i * 4];
    for (int i = tid; i < TM * (HID / 4); i += 256) {
        int r  = i >> 4;
        int c4 = (i & 15) * 4;
        int node = row0 + r;
        float4 v = make_float4(0.f, 0.f, 0.f, 0.f);
        if (node < N_NODES) {
            float di = g_dinv[node];
            float dd = di * di;
            float4 xwv = *(const float4*)&g_xw[node * HID + c4];
            uint2 mraw  = *(const uint2*)&g_h1h[node * HID + c4];
            float2 m01 = __half22float2(*reinterpret_cast<const __half2*>(&mraw.x));
            float2 m23 = __half22float2(*reinterpret_cast<const __half2*>(&mraw.y));
            float4 bb = *(const float4*)&b1[c4];
            v = make_float4(fmaxf(m01.x + dd*xwv.x + bb.x, 0.f),
                            fmaxf(m01.y + dd*xwv.y + bb.y, 0.f),
                            fmaxf(m23.x + dd*xwv.z + bb.z, 0.f),
                            fmaxf(m23.y + dd*xwv.w + bb.w, 0.f));
        }
        *(float4*)&Xs[r * HID + c4] = v;
    }
    __syncthreads();

    int ty = tid >> 4;
    int tx = tid & 15;
    float4 acc0 = make_float4(0,0,0,0), acc1 = acc0, acc2 = acc0, acc3 = acc0;
    const float* xrow = &Xs[(ty * 4) * HID];
    #pragma unroll 4
    for (int k = 0; k < HID; k++) {
        float4 w = *(const float4*)&Ws[k * HID + tx * 4];
        float x0 = xrow[k];
        float x1 = xrow[HID + k];
        float x2 = xrow[2 * HID + k];
        float x3 = xrow[3 * HID + k];
        acc0.x += x0*w.x; acc0.y += x0*w.y; acc0.z += x0*w.z; acc0.w += x0*w.w;
        acc1.x += x1*w.x; acc1.y += x1*w.y; acc1.z += x1*w.z; acc1.w += x1*w.w;
        acc2.x += x2*w.x; acc2.y += x2*w.y; acc2.z += x2*w.z; acc2.w += x2*w.w;
        acc3.x += x3*w.x; acc3.y += x3*w.y; acc3.z += x3*w.z; acc3.w += x3*w.w;
    }
    float4 bb = *(const float4*)&b2[tx * 4];
    float4 accs[4] = {acc0, acc1, acc2, acc3};
    #pragma unroll
    for (int i = 0; i < 4; i++) {
        int node = row0 + ty * 4 + i;
        if (node < N_NODES) {
            __half2 p01 = __floats2half2_rn(accs[i].x, accs[i].y);
            __half2 p23 = __floats2half2_rn(accs[i].z, accs[i].w);
            uint2 praw;
            praw.x = *(const unsigned*)&p01;
            praw.y = *(const unsigned*)&p23;
            *(uint2*)&g_h2h[node * HID + tx * 4] = praw;
            float di = g_dinv[node];
            float dd = di * di;
            __half2 s01 = __floats2half2_rn(dd*accs[i].x + bb.x, dd*accs[i].y + bb.y);
            __half2 s23 = __floats2half2_rn(dd*accs[i].z + bb.z, dd*accs[i].w + bb.w);
            uint2 sraw;
            sraw.x = *(const unsigned*)&s01;
            sraw.y = *(const unsigned*)&s23;
            *(uint2*)&g_h3h[node * HID + tx * 4] = sraw;
        }
    }
}

// ---------------- edge scatter (fp16 gather + fp16 RED, 8ch/thread) ---------
// 8 threads per edge (8 channels each); 4 independent edges per thread.
__global__ void __launch_bounds__(256) scatter_kernel(const int* __restrict__ src,
                                                      const int* __restrict__ dst,
                                                      const __half* __restrict__ in,
                                                      __half* __restrict__ out) {
    int idx = blockIdx.x * blockDim.x + threadIdx.x;   // < EQ4*8 = 1.6M
    if (idx >= EQ4 * 8) return;
    int e0 = idx >> 3;
    int c8 = (idx & 7) * 8;

    float cf[4];
    int   s[4], d[4];
    #pragma unroll
    for (int j = 0; j < 4; j++) {
        int e = e0 + j * EQ4;
        cf[j] = g_coef[e];
        s[j]  = src[e];
        d[j]  = dst[e];
    }
    uint4 raw[4];
    #pragma unroll
    for (int j = 0; j < 4; j++)
        raw[j] = *(const uint4*)(in + (long long)s[j] * HID + c8);
    #pragma unroll
    for (int j = 0; j < 4; j++) {
        __half2 ch = __float2half2_rn(cf[j]);
        __half2 m0 = __hmul2(*reinterpret_cast<const __half2*>(&raw[j].x), ch);
        __half2 m1 = __hmul2(*reinterpret_cast<const __half2*>(&raw[j].y), ch);
        __half2 m2 = __hmul2(*reinterpret_cast<const __half2*>(&raw[j].z), ch);
        __half2 m3 = __hmul2(*reinterpret_cast<const __half2*>(&raw[j].w), ch);
        red_add_v4f16x2(out + (long long)d[j] * HID + c8,
                        *(const unsigned*)&m0, *(const unsigned*)&m1,
                        *(const unsigned*)&m2, *(const unsigned*)&m3);
    }
}

// ---------------- pooling (reads fp16 h3, fp32 RED into pool) ---------------
__global__ void pool_kernel(const int* __restrict__ batch) {
    int idx = blockIdx.x * blockDim.x + threadIdx.x;
    if (idx < N_NODES * 16) {
        int i  = idx >> 4;
        int c4 = (idx & 15) * 4;
        int g = batch[i];
        uint2 raw = *(const uint2*)&g_h3h[i * HID + c4];
        float2 v01 = __half22float2(*reinterpret_cast<const __half2*>(&raw.x));
        float2 v23 = __half22float2(*reinterpret_cast<const __half2*>(&raw.y));
        red_add_v4f32(&g_pool[g * HID + c4], v01.x, v01.y, v23.x, v23.y);
    }
}

// ---------------- head ----------------
__global__ void head_kernel(const float* __restrict__ LW1,
                            const float* __restrict__ Lb1,
                            const float* __restrict__ LW2,
                            const float* __restrict__ Lb2,
                            float* __restrict__ out) {
    int g = blockIdx.x;
    int t = threadIdx.x;
    __shared__ float p[HID];
    __shared__ float h[32];
    float cnt = fmaxf(g_cnt[g], 1.0f);
    p[t]      = g_pool[g * HID + t] / cnt;
    p[t + 32] = g_pool[g * HID + 32 + t] / cnt;
    __syncwarp();
    float acc = Lb1[t];
    #pragma unroll
    for (int k = 0; k < HID; k++) acc += p[k] * LW1[k * 32 + t];
    h[t] = acc;
    __syncwarp();
    if (t < 10) {
        float o = Lb2[t];
        #pragma unroll
        for (int j = 0; j < 32; j++) o += h[j] * LW2[j * 10 + t];
        out[g * 10 + t] = o;
    }
}

// ---------------- launch ----------------
extern "C" void kernel_launch(void* const* d_in, const int* in_sizes, int n_in,
                              void* d_out, int out_size) {
    const float* x     = (const float*)d_in[0];
    const int*   ei    = (const int*)d_in[1];
    const float* ew    = (const float*)d_in[2];
    const int*   batch = (const int*)d_in[3];
    const float* W1    = (const float*)d_in[4];
    const float* b1    = (const float*)d_in[5];
    const float* W2    = (const float*)d_in[6];
    const float* b2    = (const float*)d_in[7];
    const float* LW1   = (const float*)d_in[8];
    const float* Lb1   = (const float*)d_in[9];
    const float* LW2   = (const float*)d_in[10];
    const float* Lb2   = (const float*)d_in[11];
    float* out = (float*)d_out;

    const int* src = ei;
    const int* dst = ei + N_EDGES;

    void *p_deg, *p_pool, *p_cnt, *p_h1h;
    cudaGetSymbolAddress(&p_deg,  g_deg);
    cudaGetSymbolAddress(&p_pool, g_pool);
    cudaGetSymbolAddress(&p_cnt,  g_cnt);
    cudaGetSymbolAddress(&p_h1h,  g_h1h);

    __half *xwh, *h1h, *h2h, *h3h;
    cudaGetSymbolAddress((void**)&xwh, g_xwh);
    cudaGetSymbolAddress((void**)&h1h, g_h1h);
    cudaGetSymbolAddress((void**)&h2h, g_h2h);
    cudaGetSymbolAddress((void**)&h3h, g_h3h);

    static cudaStream_t s1 = nullptr;
    static cudaEvent_t evFork = nullptr, evJoin = nullptr;
    static bool init_done = false;
    if (!init_done) {
        cudaStreamCreateWithFlags(&s1, cudaStreamNonBlocking);
        cudaEventCreateWithFlags(&evFork, cudaEventDisableTiming);
        cudaEventCreateWithFlags(&evJoin, cudaEventDisableTiming);
        cudaFuncSetAttribute(gemm1_kernel,
                             cudaFuncAttributePreferredSharedMemoryCarveout, 100);
        cudaFuncSetAttribute(gemm2_kernel,
                             cudaFuncAttributePreferredSharedMemoryCarveout, 100);
        init_done = true;
    }

    // ---- fork: prep chain on s1 runs concurrently with gemm1 on stream 0 ----
    cudaEventRecord(evFork, 0);
    cudaStreamWaitEvent(s1, evFork, 0);

    cudaMemsetAsync(p_deg,  0, N_NODES * sizeof(float), s1);
    cudaMemsetAsync(p_h1h,  0, N_NODES * HID * sizeof(__half), s1);  // msg accumulator
    cudaMemsetAsync(p_pool, 0, N_GRAPHS * HID * sizeof(float), s1);
    cudaMemsetAsync(p_cnt,  0, N_GRAPHS * sizeof(float), s1);
    deg_kernel<<<(N_EDGES + 255) / 256, 256, 0, s1>>>(dst, ew);
    dinv_kernel<<<(N_NODES + 255) / 256, 256, 0, s1>>>();
    coef_kernel<<<(N_EDGES + 255) / 256, 256, 0, s1>>>(src, dst, ew);
    cnt_kernel<<<(N_NODES + 255) / 256, 256, 0, s1>>>(batch);
    cudaEventRecord(evJoin, s1);

    int gblocks = (N_NODES + TM - 1) / TM;

    gemm1_kernel<<<gblocks, 256>>>(x, W1);          // no dinv dependency

    cudaStreamWaitEvent(0, evJoin, 0);              // join: dinv/coef/memsets ready

    scatter_kernel<<<(EQ4 * 8 + 255) / 256, 256>>>(src, dst, xwh, h1h);

    gemm2_kernel<<<gblocks, 256>>>(W2, b1, b2);
    scatter_kernel<<<(EQ4 * 8 + 255) / 256, 256>>>(src, dst, h2h, h3h);

    pool_kernel<<<(N_NODES * 16 + 255) / 256, 256>>>(batch);
    head_kernel<<<N_GRAPHS, 32>>>(LW1, Lb1, LW2, Lb2, out);
}

// round 17
// speedup vs baseline: 1.5528x; 1.1665x over previous
#include <cuda_runtime.h>
#include <cuda_fp16.h>
#include <mma.h>

using namespace nvcuda;

#define N_NODES 50000
#define N_EDGES 800000
#define N_GRAPHS 512
#define IN_CH 128
#define HID 64
#define EQ4 (N_EDGES / 4)
#define TM 64

// ---------------- scratch (device globals) ----------------
__device__ float  g_xw[N_NODES * HID];    // fp32 xW1 (self-loop term)
__device__ __half g_xwh[N_NODES * HID];   // fp16 xW1 (gather payload)
__device__ __half g_h1h[N_NODES * HID];   // fp16 conv1 message sums
__device__ __half g_h2h[N_NODES * HID];   // fp16 relu(h1)W2 (gather payload)
__device__ __half g_h3h[N_NODES * HID];   // fp16 conv2 out
__device__ float  g_deg[N_NODES];
__device__ float  g_dinv[N_NODES];
__device__ float  g_coef[N_EDGES];
__device__ float  g_pool[N_GRAPHS * HID];
__device__ float  g_cnt[N_GRAPHS];

__device__ __forceinline__ void red_add_v4f32(float* addr, float a, float b,
                                              float c, float d) {
    asm volatile("red.global.add.v4.f32 [%0], {%1, %2, %3, %4};"
                 :: "l"(addr), "f"(a), "f"(b), "f"(c), "f"(d) : "memory");
}

__device__ __forceinline__ void red_add_v4f16x2(__half* addr, unsigned r0,
                                                unsigned r1, unsigned r2,
                                                unsigned r3) {
    asm volatile("red.global.add.noftz.v4.f16x2 [%0], {%1, %2, %3, %4};"
                 :: "l"(addr), "r"(r0), "r"(r1), "r"(r2), "r"(r3) : "memory");
}

// ---------------- degree / norm (side stream) ----------------
__global__ void deg_kernel(const int* __restrict__ dst,
                           const float* __restrict__ ew) {
    int e = blockIdx.x * blockDim.x + threadIdx.x;
    if (e < N_EDGES) atomicAdd(&g_deg[dst[e]], ew[e]);
}

__global__ void dinv_kernel() {
    int i = blockIdx.x * blockDim.x + threadIdx.x;
    if (i < N_NODES) g_dinv[i] = rsqrtf(g_deg[i] + 1.0f);
}

__global__ void coef_kernel(const int* __restrict__ src,
                            const int* __restrict__ dst,
                            const float* __restrict__ ew) {
    int e = blockIdx.x * blockDim.x + threadIdx.x;
    if (e < N_EDGES)
        g_coef[e] = g_dinv[src[e]] * ew[e] * g_dinv[dst[e]];
}

// ---------------- GEMM 1 (fp16 HMMA, fp32 accum): [N,128]@[128,64] ----------
// 256 threads = 8 warps; warp w: rows (w>>1)*16, cols (w&1)*32 (2 tiles).
// Padded fp16 smem: Xh stride 136, Wh stride 72 (both 16B-aligned rows).
#define XLD 136
#define WLD 72
__global__ void __launch_bounds__(256) gemm1_kernel(const float* __restrict__ x,
                                                    const float* __restrict__ W) {
    __shared__ __half sm[TM * XLD + IN_CH * WLD];   // 35840 B
    __half* Xh = sm;
    __half* Wh = sm + TM * XLD;
    int tid = threadIdx.x;
    int wid = tid >> 5;
    int row0 = blockIdx.x * TM;

    // stage x rows (fp32 -> fp16)
    for (int i = tid; i < TM * (IN_CH / 4); i += 256) {
        int r  = i >> 5;
        int c4 = (i & 31) * 4;
        int node = row0 + r;
        float4 v = (node < N_NODES)
                 ? *(const float4*)&x[(long long)node * IN_CH + c4]
                 : make_float4(0.f, 0.f, 0.f, 0.f);
        __half2 h01 = __floats2half2_rn(v.x, v.y);
        __half2 h23 = __floats2half2_rn(v.z, v.w);
        uint2 raw;
        raw.x = *(const unsigned*)&h01;
        raw.y = *(const unsigned*)&h23;
        *(uint2*)&Xh[r * XLD + c4] = raw;
    }
    // stage W (fp32 -> fp16)
    for (int i = tid; i < IN_CH * (HID / 4); i += 256) {
        int k  = i >> 4;
        int c4 = (i & 15) * 4;
        float4 v = *(const float4*)&W[k * HID + c4];
        __half2 h01 = __floats2half2_rn(v.x, v.y);
        __half2 h23 = __floats2half2_rn(v.z, v.w);
        uint2 raw;
        raw.x = *(const unsigned*)&h01;
        raw.y = *(const unsigned*)&h23;
        *(uint2*)&Wh[k * WLD + c4] = raw;
    }
    __syncthreads();

    int rw = (wid >> 1) * 16;   // warp row tile
    int cw = (wid & 1) * 32;    // warp col base (2 x 16 tiles)

    wmma::fragment<wmma::matrix_a, 16, 16, 16, __half, wmma::row_major> a;
    wmma::fragment<wmma::matrix_b, 16, 16, 16, __half, wmma::row_major> b0, b1;
    wmma::fragment<wmma::accumulator, 16, 16, 16, float> c0, c1;
    wmma::fill_fragment(c0, 0.0f);
    wmma::fill_fragment(c1, 0.0f);

    #pragma unroll
    for (int k = 0; k < IN_CH; k += 16) {
        wmma::load_matrix_sync(a, &Xh[rw * XLD + k], XLD);
        wmma::load_matrix_sync(b0, &Wh[k * WLD + cw], WLD);
        wmma::load_matrix_sync(b1, &Wh[k * WLD + cw + 16], WLD);
        wmma::mma_sync(c0, a, b0, c0);
        wmma::mma_sync(c1, a, b1, c1);
    }

    // overlay result tile on the (now dead) fp16 staging area
    __syncthreads();
    float* Cs = (float*)sm;    // 64*64*4 = 16 KB < 35.8 KB
    wmma::store_matrix_sync(&Cs[rw * HID + cw], c0, HID, wmma::mem_row_major);
    wmma::store_matrix_sync(&Cs[rw * HID + cw + 16], c1, HID, wmma::mem_row_major);
    __syncthreads();

    for (int i = tid; i < TM * (HID / 4); i += 256) {
        int r  = i >> 4;
        int c4 = (i & 15) * 4;
        int node = row0 + r;
        if (node < N_NODES) {
            float4 acc = *(const float4*)&Cs[r * HID + c4];
            *(float4*)&g_xw[node * HID + c4] = acc;
            __half2 h01 = __floats2half2_rn(acc.x, acc.y);
            __half2 h23 = __floats2half2_rn(acc.z, acc.w);
            uint2 raw;
            raw.x = *(const unsigned*)&h01;
            raw.y = *(const unsigned*)&h23;
            *(uint2*)&g_xwh[node * HID + c4] = raw;
        }
    }
}

// ---------------- GEMM 2 (fp32 SIMT): in = relu(h1msg + dinv^2*xw + b1) -----
__global__ void __launch_bounds__(256) gemm2_kernel(const float* __restrict__ W,
                                                    const float* __restrict__ b1,
                                                    const float* __restrict__ b2) {
    __shared__ float Ws[HID * HID];
    __shared__ float Xs[TM * HID];
    int tid = threadIdx.x;
    int row0 = blockIdx.x * TM;

    for (int i = tid; i < HID * HID / 4; i += 256)
        *(float4*)&Ws[i * 4] = *(const float4*)&W[i * 4];
    for (int i = tid; i < TM * (HID / 4); i += 256) {
        int r  = i >> 4;
        int c4 = (i & 15) * 4;
        int node = row0 + r;
        float4 v = make_float4(0.f, 0.f, 0.f, 0.f);
        if (node < N_NODES) {
            float di = g_dinv[node];
            float dd = di * di;
            float4 xwv = *(const float4*)&g_xw[node * HID + c4];
            uint2 mraw  = *(const uint2*)&g_h1h[node * HID + c4];
            float2 m01 = __half22float2(*reinterpret_cast<const __half2*>(&mraw.x));
            float2 m23 = __half22float2(*reinterpret_cast<const __half2*>(&mraw.y));
            float4 bb = *(const float4*)&b1[c4];
            v = make_float4(fmaxf(m01.x + dd*xwv.x + bb.x, 0.f),
                            fmaxf(m01.y + dd*xwv.y + bb.y, 0.f),
                            fmaxf(m23.x + dd*xwv.z + bb.z, 0.f),
                            fmaxf(m23.y + dd*xwv.w + bb.w, 0.f));
        }
        *(float4*)&Xs[r * HID + c4] = v;
    }
    __syncthreads();

    int ty = tid >> 4;
    int tx = tid & 15;
    float4 acc0 = make_float4(0,0,0,0), acc1 = acc0, acc2 = acc0, acc3 = acc0;
    const float* xrow = &Xs[(ty * 4) * HID];
    #pragma unroll 4
    for (int k = 0; k < HID; k++) {
        float4 w = *(const float4*)&Ws[k * HID + tx * 4];
        float x0 = xrow[k];
        float x1 = xrow[HID + k];
        float x2 = xrow[2 * HID + k];
        float x3 = xrow[3 * HID + k];
        acc0.x += x0*w.x; acc0.y += x0*w.y; acc0.z += x0*w.z; acc0.w += x0*w.w;
        acc1.x += x1*w.x; acc1.y += x1*w.y; acc1.z += x1*w.z; acc1.w += x1*w.w;
        acc2.x += x2*w.x; acc2.y += x2*w.y; acc2.z += x2*w.z; acc2.w += x2*w.w;
        acc3.x += x3*w.x; acc3.y += x3*w.y; acc3.z += x3*w.z; acc3.w += x3*w.w;
    }
    float4 bb = *(const float4*)&b2[tx * 4];
    float4 accs[4] = {acc0, acc1, acc2, acc3};
    #pragma unroll
    for (int i = 0; i < 4; i++) {
        int node = row0 + ty * 4 + i;
        if (node < N_NODES) {
            __half2 p01 = __floats2half2_rn(accs[i].x, accs[i].y);
            __half2 p23 = __floats2half2_rn(accs[i].z, accs[i].w);
            uint2 praw;
            praw.x = *(const unsigned*)&p01;
            praw.y = *(const unsigned*)&p23;
            *(uint2*)&g_h2h[node * HID + tx * 4] = praw;
            float di = g_dinv[node];
            float dd = di * di;
            __half2 s01 = __floats2half2_rn(dd*accs[i].x + bb.x, dd*accs[i].y + bb.y);
            __half2 s23 = __floats2half2_rn(dd*accs[i].z + bb.z, dd*accs[i].w + bb.w);
            uint2 sraw;
            sraw.x = *(const unsigned*)&s01;
            sraw.y = *(const unsigned*)&s23;
            *(uint2*)&g_h3h[node * HID + tx * 4] = sraw;
        }
    }
}

// ---------------- edge scatter (fp16 gather + fp16 RED, 8ch/thread) ---------
__global__ void __launch_bounds__(256) scatter_kernel(const int* __restrict__ src,
                                                      const int* __restrict__ dst,
                                                      const __half* __restrict__ in,
                                                      __half* __restrict__ out) {
    int idx = blockIdx.x * blockDim.x + threadIdx.x;   // < EQ4*8 = 1.6M
    if (idx >= EQ4 * 8) return;
    int e0 = idx >> 3;
    int c8 = (idx & 7) * 8;

    float cf[4];
    int   s[4], d[4];
    #pragma unroll
    for (int j = 0; j < 4; j++) {
        int e = e0 + j * EQ4;
        cf[j] = g_coef[e];
        s[j]  = src[e];
        d[j]  = dst[e];
    }
    uint4 raw[4];
    #pragma unroll
    for (int j = 0; j < 4; j++)
        raw[j] = *(const uint4*)(in + (long long)s[j] * HID + c8);
    #pragma unroll
    for (int j = 0; j < 4; j++) {
        __half2 ch = __float2half2_rn(cf[j]);
        __half2 m0 = __hmul2(*reinterpret_cast<const __half2*>(&raw[j].x), ch);
        __half2 m1 = __hmul2(*reinterpret_cast<const __half2*>(&raw[j].y), ch);
        __half2 m2 = __hmul2(*reinterpret_cast<const __half2*>(&raw[j].z), ch);
        __half2 m3 = __hmul2(*reinterpret_cast<const __half2*>(&raw[j].w), ch);
        red_add_v4f16x2(out + (long long)d[j] * HID + c8,
                        *(const unsigned*)&m0, *(const unsigned*)&m1,
                        *(const unsigned*)&m2, *(const unsigned*)&m3);
    }
}

// ---------------- pooling (reads fp16 h3, fp32 RED; counts at c4==0) --------
__global__ void pool_kernel(const int* __restrict__ batch) {
    int idx = blockIdx.x * blockDim.x + threadIdx.x;
    if (idx < N_NODES * 16) {
        int i  = idx >> 4;
        int c4 = (idx & 15) * 4;
        int g = batch[i];
        uint2 raw = *(const uint2*)&g_h3h[i * HID + c4];
        float2 v01 = __half22float2(*reinterpret_cast<const __half2*>(&raw.x));
        float2 v23 = __half22float2(*reinterpret_cast<const __half2*>(&raw.y));
        red_add_v4f32(&g_pool[g * HID + c4], v01.x, v01.y, v23.x, v23.y);
        if (c4 == 0) atomicAdd(&g_cnt[g], 1.0f);
    }
}

// ---------------- head ----------------
__global__ void head_kernel(const float* __restrict__ LW1,
                            const float* __restrict__ Lb1,
                            const float* __restrict__ LW2,
                            const float* __restrict__ Lb2,
                            float* __restrict__ out) {
    int g = blockIdx.x;
    int t = threadIdx.x;
    __shared__ float p[HID];
    __shared__ float h[32];
    float cnt = fmaxf(g_cnt[g], 1.0f);
    p[t]      = g_pool[g * HID + t] / cnt;
    p[t + 32] = g_pool[g * HID + 32 + t] / cnt;
    __syncwarp();
    float acc = Lb1[t];
    #pragma unroll
    for (int k = 0; k < HID; k++) acc += p[k] * LW1[k * 32 + t];
    h[t] = acc;
    __syncwarp();
    if (t < 10) {
        float o = Lb2[t];
        #pragma unroll
        for (int j = 0; j < 32; j++) o += h[j] * LW2[j * 10 + t];
        out[g * 10 + t] = o;
    }
}

// ---------------- launch ----------------
extern "C" void kernel_launch(void* const* d_in, const int* in_sizes, int n_in,
                              void* d_out, int out_size) {
    const float* x     = (const float*)d_in[0];
    const int*   ei    = (const int*)d_in[1];
    const float* ew    = (const float*)d_in[2];
    const int*   batch = (const int*)d_in[3];
    const float* W1    = (const float*)d_in[4];
    const float* b1    = (const float*)d_in[5];
    const float* W2    = (const float*)d_in[6];
    const float* b2    = (const float*)d_in[7];
    const float* LW1   = (const float*)d_in[8];
    const float* Lb1   = (const float*)d_in[9];
    const float* LW2   = (const float*)d_in[10];
    const float* Lb2   = (const float*)d_in[11];
    float* out = (float*)d_out;

    const int* src = ei;
    const int* dst = ei + N_EDGES;

    void *p_deg, *p_pool, *p_cnt, *p_h1h;
    cudaGetSymbolAddress(&p_deg,  g_deg);
    cudaGetSymbolAddress(&p_pool, g_pool);
    cudaGetSymbolAddress(&p_cnt,  g_cnt);
    cudaGetSymbolAddress(&p_h1h,  g_h1h);

    __half *xwh, *h1h, *h2h, *h3h;
    cudaGetSymbolAddress((void**)&xwh, g_xwh);
    cudaGetSymbolAddress((void**)&h1h, g_h1h);
    cudaGetSymbolAddress((void**)&h2h, g_h2h);
    cudaGetSymbolAddress((void**)&h3h, g_h3h);

    static cudaStream_t s1 = nullptr;
    static cudaEvent_t evFork = nullptr, evJoin = nullptr;
    static bool init_done = false;
    if (!init_done) {
        cudaStreamCreateWithFlags(&s1, cudaStreamNonBlocking);
        cudaEventCreateWithFlags(&evFork, cudaEventDisableTiming);
        cudaEventCreateWithFlags(&evJoin, cudaEventDisableTiming);
        cudaFuncSetAttribute(gemm1_kernel,
                             cudaFuncAttributePreferredSharedMemoryCarveout, 100);
        cudaFuncSetAttribute(gemm2_kernel,
                             cudaFuncAttributePreferredSharedMemoryCarveout, 100);
        init_done = true;
    }

    // ---- fork: prep chain on s1 runs concurrently with gemm1 on stream 0 ----
    cudaEventRecord(evFork, 0);
    cudaStreamWaitEvent(s1, evFork, 0);

    cudaMemsetAsync(p_deg,  0, N_NODES * sizeof(float), s1);
    cudaMemsetAsync(p_h1h,  0, N_NODES * HID * sizeof(__half), s1);
    cudaMemsetAsync(p_pool, 0, N_GRAPHS * HID * sizeof(float), s1);
    cudaMemsetAsync(p_cnt,  0, N_GRAPHS * sizeof(float), s1);
    deg_kernel<<<(N_EDGES + 255) / 256, 256, 0, s1>>>(dst, ew);
    dinv_kernel<<<(N_NODES + 255) / 256, 256, 0, s1>>>();
    coef_kernel<<<(N_EDGES + 255) / 256, 256, 0, s1>>>(src, dst, ew);
    cudaEventRecord(evJoin, s1);

    int gblocks = (N_NODES + TM - 1) / TM;

    gemm1_kernel<<<gblocks, 256>>>(x, W1);          // no dinv dependency

    cudaStreamWaitEvent(0, evJoin, 0);              // join: dinv/coef/memsets ready

    scatter_kernel<<<(EQ4 * 8 + 255) / 256, 256>>>(src, dst, xwh, h1h);

    gemm2_kernel<<<gblocks, 256>>>(W2, b1, b2);
    scatter_kernel<<<(EQ4 * 8 + 255) / 256, 256>>>(src, dst, h2h, h3h);

    pool_kernel<<<(N_NODES * 16 + 255) / 256, 256>>>(batch);
    head_kernel<<<N_GRAPHS, 32>>>(LW1, Lb1, LW2, Lb2, out);
}